// round 2
// baseline (speedup 1.0000x reference)
#include <cuda_runtime.h>
#include <cuda_bf16.h>
#include <math.h>

// Problem constants
#define HEADS 16
#define DMODEL 1024
#define KDIM 64
#define MFF 4096
#define MEMLEN 3
#define SEQ 512
#define BATCH 4
#define NROWS (SEQ * BATCH)            // 2048
#define LTOT ((MEMLEN + 1) * SEQ)      // 2048
#define KVROWS (LTOT * BATCH)          // 8192

// ---------------- scratch (no allocation allowed) ----------------
__device__ float g_q[NROWS * DMODEL];
__device__ float g_k[KVROWS * DMODEL];
__device__ float g_v[KVROWS * DMODEL];
__device__ float g_av[NROWS * DMODEL];
__device__ float g_upre[NROWS * DMODEL];
__device__ float g_u[NROWS * DMODEL];
__device__ float g_ff[NROWS * MFF];

// ---------------- generic tiled GEMM: C = rowcat(A,A2) @ W^T (+bias)(+res)(relu) ----------------
// A rows < split come from A, rows >= split come from A2 (row - split).
// M, N, Kd all multiples of 64/16 for this problem; no bounds checks.
#define BM 64
#define BN 64
#define BKK 16

__global__ __launch_bounds__(256) void gemm_kernel(
    const float* __restrict__ A, const float* __restrict__ A2, int split,
    const float* __restrict__ W, const float* __restrict__ bias,
    const float* __restrict__ res, float* __restrict__ C,
    int M, int N, int Kd, int relu)
{
    __shared__ __align__(16) float As[BKK][BM + 4];   // [k][m]
    __shared__ __align__(16) float Ws[BKK][BN + 4];   // [k][n]

    const int tx = threadIdx.x % 16;
    const int ty = threadIdx.x / 16;
    const int bm = blockIdx.y * BM;
    const int bn = blockIdx.x * BN;

    const int lr = threadIdx.x / 4;        // 0..63
    const int lk = (threadIdx.x % 4) * 4;  // 0,4,8,12

    const int arow = bm + lr;
    const float* Arow = (arow < split) ? (A + (long)arow * Kd)
                                       : (A2 + (long)(arow - split) * Kd);
    const float* Wrow = W + (long)(bn + lr) * Kd;

    float acc[4][4] = {};

    for (int k0 = 0; k0 < Kd; k0 += BKK) {
        float4 va = *(const float4*)(Arow + k0 + lk);
        float4 vb = *(const float4*)(Wrow + k0 + lk);
        As[lk + 0][lr] = va.x; As[lk + 1][lr] = va.y;
        As[lk + 2][lr] = va.z; As[lk + 3][lr] = va.w;
        Ws[lk + 0][lr] = vb.x; Ws[lk + 1][lr] = vb.y;
        Ws[lk + 2][lr] = vb.z; Ws[lk + 3][lr] = vb.w;
        __syncthreads();

#pragma unroll
        for (int kk = 0; kk < BKK; ++kk) {
            float4 ra = *(const float4*)&As[kk][ty * 4];
            float4 rb = *(const float4*)&Ws[kk][tx * 4];
            float a0 = ra.x, a1 = ra.y, a2 = ra.z, a3 = ra.w;
            float b0 = rb.x, b1 = rb.y, b2 = rb.z, b3 = rb.w;
            acc[0][0] += a0 * b0; acc[0][1] += a0 * b1; acc[0][2] += a0 * b2; acc[0][3] += a0 * b3;
            acc[1][0] += a1 * b0; acc[1][1] += a1 * b1; acc[1][2] += a1 * b2; acc[1][3] += a1 * b3;
            acc[2][0] += a2 * b0; acc[2][1] += a2 * b1; acc[2][2] += a2 * b2; acc[2][3] += a2 * b3;
            acc[3][0] += a3 * b0; acc[3][1] += a3 * b1; acc[3][2] += a3 * b2; acc[3][3] += a3 * b3;
        }
        __syncthreads();
    }

#pragma unroll
    for (int i = 0; i < 4; ++i) {
        int row = bm + ty * 4 + i;
#pragma unroll
        for (int j = 0; j < 4; ++j) {
            int col = bn + tx * 4 + j;
            float vv = acc[i][j];
            if (bias) vv += bias[col];
            if (res)  vv += res[(long)row * N + col];
            if (relu) vv = fmaxf(vv, 0.0f);
            C[(long)row * N + col] = vv;
        }
    }
}

// ---------------- flash attention: per (h,b), S-tile=64, L-chunks of 32 ----------------
#define AS 64
#define AL 32

__global__ __launch_bounds__(256) void attn_kernel(
    const float* __restrict__ q, const float* __restrict__ k,
    const float* __restrict__ v, const float* __restrict__ mask,
    float* __restrict__ av)
{
    __shared__ float q_s[AS][65];
    __shared__ float k_s[AL][65];
    __shared__ float v_s[AL][65];
    __shared__ float p_s[AS][AL + 1];
    __shared__ float m_sm[AS], l_sm[AS], c_sm[AS];

    const int hb = blockIdx.y;            // 0..63
    const int h = hb / BATCH, b = hb % BATCH;
    const int s0 = blockIdx.x * AS;
    const int tid = threadIdx.x;
    const int lane = tid & 31, warp = tid >> 5;
    const int tx = tid % 16, ty = tid / 16;

    // load Q tile: q[(s*B+b)*D + h*64 + c]
    for (int e = tid; e < AS * 64; e += 256) {
        int r = e >> 6, c = e & 63;
        q_s[r][c] = q[((long)(s0 + r) * BATCH + b) * DMODEL + h * 64 + c];
    }
    if (tid < AS) { m_sm[tid] = -1e30f; l_sm[tid] = 0.0f; }
    float acc[4][4] = {};
    __syncthreads();

    for (int l0 = 0; l0 < LTOT; l0 += AL) {
        for (int e = tid; e < AL * 64; e += 256) {
            int r = e >> 6, c = e & 63;
            long base = ((long)(l0 + r) * BATCH + b) * DMODEL + h * 64 + c;
            k_s[r][c] = k[base];
            v_s[r][c] = v[base];
        }
        __syncthreads();

        // scores: each warp owns 8 S-rows; lane = L-column within chunk
#pragma unroll
        for (int r0 = 0; r0 < 8; ++r0) {
            int r = warp * 8 + r0;
            float sc = 0.0f;
#pragma unroll
            for (int c = 0; c < 64; ++c) sc += q_s[r][c] * k_s[lane][c];
            sc = sc * 0.125f + mask[(long)(s0 + r) * LTOT + l0 + lane];

            float mx = sc;
#pragma unroll
            for (int o = 16; o > 0; o >>= 1) mx = fmaxf(mx, __shfl_xor_sync(0xffffffffu, mx, o));
            float m_old = m_sm[r];
            float m_new = fmaxf(m_old, mx);
            float p = __expf(sc - m_new);
            float ps = p;
#pragma unroll
            for (int o = 16; o > 0; o >>= 1) ps += __shfl_xor_sync(0xffffffffu, ps, o);
            if (lane == 0) {
                float cf = __expf(m_old - m_new);
                c_sm[r] = cf;
                l_sm[r] = l_sm[r] * cf + ps;
                m_sm[r] = m_new;
            }
            p_s[r][lane] = p;
        }
        __syncthreads();

        // acc = acc*c + P @ V   (thread tile 4 rows x 4 kd)
        float cf0 = c_sm[ty * 4 + 0], cf1 = c_sm[ty * 4 + 1];
        float cf2 = c_sm[ty * 4 + 2], cf3 = c_sm[ty * 4 + 3];
#pragma unroll
        for (int j = 0; j < 4; ++j) {
            acc[0][j] *= cf0; acc[1][j] *= cf1; acc[2][j] *= cf2; acc[3][j] *= cf3;
        }
#pragma unroll
        for (int l = 0; l < AL; ++l) {
            float p0 = p_s[ty * 4 + 0][l], p1 = p_s[ty * 4 + 1][l];
            float p2 = p_s[ty * 4 + 2][l], p3 = p_s[ty * 4 + 3][l];
            float v0 = v_s[l][tx * 4 + 0], v1 = v_s[l][tx * 4 + 1];
            float v2 = v_s[l][tx * 4 + 2], v3 = v_s[l][tx * 4 + 3];
            acc[0][0] += p0 * v0; acc[0][1] += p0 * v1; acc[0][2] += p0 * v2; acc[0][3] += p0 * v3;
            acc[1][0] += p1 * v0; acc[1][1] += p1 * v1; acc[1][2] += p1 * v2; acc[1][3] += p1 * v3;
            acc[2][0] += p2 * v0; acc[2][1] += p2 * v1; acc[2][2] += p2 * v2; acc[2][3] += p2 * v3;
            acc[3][0] += p3 * v0; acc[3][1] += p3 * v1; acc[3][2] += p3 * v2; acc[3][3] += p3 * v3;
        }
        __syncthreads();
    }

#pragma unroll
    for (int i = 0; i < 4; ++i) {
        int r = ty * 4 + i;
        float inv = 1.0f / l_sm[r];
#pragma unroll
        for (int j = 0; j < 4; ++j) {
            av[((long)(s0 + r) * BATCH + b) * DMODEL + h * 64 + tx * 4 + j] = acc[i][j] * inv;
        }
    }
}

// ---------------- LayerNorm over D=1024, one block per row ----------------
__global__ __launch_bounds__(256) void ln_kernel(
    const float* __restrict__ in, float* __restrict__ out,
    const float* __restrict__ g, const float* __restrict__ bta)
{
    const int row = blockIdx.x;
    const float* x = in + (long)row * DMODEL;
    const int tid = threadIdx.x;
    float v[4];
    float s = 0.0f, s2 = 0.0f;
#pragma unroll
    for (int i = 0; i < 4; ++i) {
        v[i] = x[tid + i * 256];
        s += v[i];
        s2 += v[i] * v[i];
    }
    __shared__ float rs[8], rs2[8];
#pragma unroll
    for (int o = 16; o > 0; o >>= 1) {
        s  += __shfl_xor_sync(0xffffffffu, s, o);
        s2 += __shfl_xor_sync(0xffffffffu, s2, o);
    }
    if ((tid & 31) == 0) { rs[tid >> 5] = s; rs2[tid >> 5] = s2; }
    __syncthreads();
    if (tid < 32) {
        s  = (tid < 8) ? rs[tid]  : 0.0f;
        s2 = (tid < 8) ? rs2[tid] : 0.0f;
#pragma unroll
        for (int o = 4; o > 0; o >>= 1) {
            s  += __shfl_xor_sync(0xffffffffu, s, o);
            s2 += __shfl_xor_sync(0xffffffffu, s2, o);
        }
        if (tid == 0) { rs[0] = s; rs2[0] = s2; }
    }
    __syncthreads();
    float mu  = rs[0] * (1.0f / DMODEL);
    float var = rs2[0] * (1.0f / DMODEL) - mu * mu;
    float inv = rsqrtf(var + 1e-5f);
#pragma unroll
    for (int i = 0; i < 4; ++i) {
        int c = tid + i * 256;
        out[(long)row * DMODEL + c] = (v[i] - mu) * inv * g[c] + bta[c];
    }
}

// ---------------- launch ----------------
extern "C" void kernel_launch(void* const* d_in, const int* in_sizes, int n_in,
                              void* d_out, int out_size)
{
    const float* x      = (const float*)d_in[0];
    const float* mask   = (const float*)d_in[1];
    const float* memory = (const float*)d_in[2];

    // "heads" is a scalar input that may or may not appear at index 3.
    int o = 3;
    if (n_in >= 16 && in_sizes[3] == 1) o = 4;
    const float* wq   = (const float*)d_in[o + 0];
    const float* wk   = (const float*)d_in[o + 1];
    const float* wv   = (const float*)d_in[o + 2];
    const float* wc   = (const float*)d_in[o + 3];
    const float* w1   = (const float*)d_in[o + 4];
    const float* b1   = (const float*)d_in[o + 5];
    const float* w2   = (const float*)d_in[o + 6];
    const float* b2   = (const float*)d_in[o + 7];
    const float* ln1g = (const float*)d_in[o + 8];
    const float* ln1b = (const float*)d_in[o + 9];
    const float* ln2g = (const float*)d_in[o + 10];
    const float* ln2b = (const float*)d_in[o + 11];
    float* out = (float*)d_out;

    // Symbol-address lookups: pure address queries, enqueue no work —
    // safe under graph capture, deterministic across calls.
    float *q, *k, *v, *av, *upre, *u, *ff;
    cudaGetSymbolAddress((void**)&q,    g_q);
    cudaGetSymbolAddress((void**)&k,    g_k);
    cudaGetSymbolAddress((void**)&v,    g_v);
    cudaGetSymbolAddress((void**)&av,   g_av);
    cudaGetSymbolAddress((void**)&upre, g_upre);
    cudaGetSymbolAddress((void**)&u,    g_u);
    cudaGetSymbolAddress((void**)&ff,   g_ff);

    const int BIG = 1 << 30;
    dim3 thr(256);

    // Q = x @ wq^T
    gemm_kernel<<<dim3(DMODEL / BN, NROWS / BM), thr>>>(
        x, x, BIG, wq, nullptr, nullptr, q, NROWS, DMODEL, DMODEL, 0);
    // K = concat(memory, x) @ wk^T ; V likewise
    gemm_kernel<<<dim3(DMODEL / BN, KVROWS / BM), thr>>>(
        memory, x, MEMLEN * NROWS, wk, nullptr, nullptr, k, KVROWS, DMODEL, DMODEL, 0);
    gemm_kernel<<<dim3(DMODEL / BN, KVROWS / BM), thr>>>(
        memory, x, MEMLEN * NROWS, wv, nullptr, nullptr, v, KVROWS, DMODEL, DMODEL, 0);
    // attention
    attn_kernel<<<dim3(SEQ / AS, HEADS * BATCH), thr>>>(q, k, v, mask, av);
    // u_pre = av @ wc^T + x ; u = LN1(u_pre)
    gemm_kernel<<<dim3(DMODEL / BN, NROWS / BM), thr>>>(
        av, av, BIG, wc, nullptr, x, upre, NROWS, DMODEL, DMODEL, 0);
    ln_kernel<<<NROWS, 256>>>(upre, u, ln1g, ln1b);
    // ff = relu(u @ w1^T + b1)
    gemm_kernel<<<dim3(MFF / BN, NROWS / BM), thr>>>(
        u, u, BIG, w1, b1, nullptr, ff, NROWS, MFF, DMODEL, 1);
    // z_pre = ff @ w2^T + b2 + u ; out = LN2(z_pre) in-place
    gemm_kernel<<<dim3(DMODEL / BN, NROWS / BM), thr>>>(
        ff, ff, BIG, w2, b2, u, out, NROWS, DMODEL, MFF, 0);
    ln_kernel<<<NROWS, 256>>>(out, out, ln2g, ln2b);
}

// round 5
// speedup vs baseline: 1.5753x; 1.5753x over previous
#include <cuda_runtime.h>
#include <cuda_bf16.h>
#include <math.h>

// Problem constants
#define HEADS 16
#define DMODEL 1024
#define KDIM 64
#define MFF 4096
#define MEMLEN 3
#define SEQ 512
#define BATCH 4
#define NROWS (SEQ * BATCH)            // 2048
#define LTOT ((MEMLEN + 1) * SEQ)      // 2048
#define KVROWS (LTOT * BATCH)          // 8192

// ---------------- scratch (no allocation allowed) ----------------
__device__ float g_q[NROWS * DMODEL];
__device__ float g_k[KVROWS * DMODEL];
__device__ float g_v[KVROWS * DMODEL];
__device__ float g_av[NROWS * DMODEL];
__device__ float g_upre[NROWS * DMODEL];
__device__ float g_u[NROWS * DMODEL];
__device__ float g_ff[NROWS * MFF];

// =======================================================================
// Tensor-core GEMM with split-bf16 (hi+lo) for fp32-class accuracy.
// C[M,N] = rowcat(A,A2)[M,Kd] @ W[N,Kd]^T (+bias)(+res)(relu)
// BM=128, BN=64, BK=32, 256 threads (8 warps: 4 in M x 2 in N).
// =======================================================================
#define BM 128
#define BN 64
#define BK 32
#define BKP 40   // padded k-stride (80 bytes) -> conflict-free ldmatrix

__device__ __forceinline__ unsigned smem_u32(const void* p) {
    return (unsigned)__cvta_generic_to_shared(p);
}

__device__ __forceinline__ void ldm_x4(unsigned* r, unsigned addr) {
    asm volatile("ldmatrix.sync.aligned.m8n8.x4.shared.b16 {%0,%1,%2,%3}, [%4];"
                 : "=r"(r[0]), "=r"(r[1]), "=r"(r[2]), "=r"(r[3]) : "r"(addr));
}

__device__ __forceinline__ void mma_bf16(float* d, const unsigned* a,
                                         unsigned b0, unsigned b1) {
    asm volatile("mma.sync.aligned.m16n8k16.row.col.f32.bf16.bf16.f32 "
                 "{%0,%1,%2,%3}, {%4,%5,%6,%7}, {%8,%9}, {%0,%1,%2,%3};"
                 : "+f"(d[0]), "+f"(d[1]), "+f"(d[2]), "+f"(d[3])
                 : "r"(a[0]), "r"(a[1]), "r"(a[2]), "r"(a[3]), "r"(b0), "r"(b1));
}

__device__ __forceinline__ __nv_bfloat162 split_hi2(float x, float y) {
    return __nv_bfloat162(__float2bfloat16_rn(x), __float2bfloat16_rn(y));
}
__device__ __forceinline__ __nv_bfloat162 split_lo2(float x, float y,
                                                    __nv_bfloat162 h) {
    return __nv_bfloat162(
        __float2bfloat16_rn(x - __bfloat162float(h.x)),
        __float2bfloat16_rn(y - __bfloat162float(h.y)));
}

__global__ __launch_bounds__(256) void gemm_tc_kernel(
    const float* __restrict__ A, const float* __restrict__ A2, int split,
    const float* __restrict__ W, const float* __restrict__ bias,
    const float* __restrict__ res, float* __restrict__ C,
    int N, int Kd, int relu)
{
    __shared__ __align__(16) __nv_bfloat16 Ah[BM][BKP];
    __shared__ __align__(16) __nv_bfloat16 Al[BM][BKP];
    __shared__ __align__(16) __nv_bfloat16 Bh[BN][BKP];
    __shared__ __align__(16) __nv_bfloat16 Bl[BN][BKP];

    const int tid  = threadIdx.x;
    const int lane = tid & 31;
    const int warp = tid >> 5;
    const int warp_m = warp >> 1;      // 0..3, 32 rows each
    const int warp_n = warp & 1;       // 0..1, 32 cols each
    const int bm = blockIdx.y * BM;
    const int bn = blockIdx.x * BN;

    // gmem load assignment
    const int ar = tid >> 1;                 // 0..127
    const int ac = (tid & 1) * 16;           // 0 or 16
    const int br = tid >> 2;                 // 0..63
    const int bc = (tid & 3) * 8;            // 0,8,16,24

    const int garow = bm + ar;
    const float* Aptr = (garow < split) ? (A + (long)garow * Kd)
                                        : (A2 + (long)(garow - split) * Kd);
    const float* Wptr = W + (long)(bn + br) * Kd;

    float acc[2][4][4];
#pragma unroll
    for (int i = 0; i < 2; ++i)
#pragma unroll
        for (int j = 0; j < 4; ++j)
#pragma unroll
            for (int l = 0; l < 4; ++l) acc[i][j][l] = 0.0f;

    // ldmatrix source addresses (per-lane)
    const int lr16 = lane & 15;
    const int lkh  = (lane >> 4) * 8;   // 0 or 8
    unsigned a_addr[2], b_addr[2];
#pragma unroll
    for (int mi = 0; mi < 2; ++mi)
        a_addr[mi] = smem_u32(&Ah[warp_m * 32 + mi * 16 + lr16][lkh]);
#pragma unroll
    for (int nj = 0; nj < 2; ++nj)
        b_addr[nj] = smem_u32(&Bh[warp_n * 32 + nj * 16 + lr16][lkh]);
    const unsigned lo_off_a = (unsigned)((char*)&Al[0][0] - (char*)&Ah[0][0]);
    const unsigned lo_off_b = (unsigned)((char*)&Bl[0][0] - (char*)&Bh[0][0]);

    float4 av[4], bv[2];
#pragma unroll
    for (int i = 0; i < 4; ++i) av[i] = *(const float4*)(Aptr + ac + i * 4);
#pragma unroll
    for (int i = 0; i < 2; ++i) bv[i] = *(const float4*)(Wptr + bc + i * 4);

    for (int k0 = 0; k0 < Kd; k0 += BK) {
        __syncthreads();   // previous compute finished reading smem
        // convert + store current tile
#pragma unroll
        for (int i = 0; i < 4; ++i) {
            __nv_bfloat162 h0 = split_hi2(av[i].x, av[i].y);
            __nv_bfloat162 h1 = split_hi2(av[i].z, av[i].w);
            __nv_bfloat162 l0 = split_lo2(av[i].x, av[i].y, h0);
            __nv_bfloat162 l1 = split_lo2(av[i].z, av[i].w, h1);
            *(__nv_bfloat162*)&Ah[ar][ac + i * 4 + 0] = h0;
            *(__nv_bfloat162*)&Ah[ar][ac + i * 4 + 2] = h1;
            *(__nv_bfloat162*)&Al[ar][ac + i * 4 + 0] = l0;
            *(__nv_bfloat162*)&Al[ar][ac + i * 4 + 2] = l1;
        }
#pragma unroll
        for (int i = 0; i < 2; ++i) {
            __nv_bfloat162 h0 = split_hi2(bv[i].x, bv[i].y);
            __nv_bfloat162 h1 = split_hi2(bv[i].z, bv[i].w);
            __nv_bfloat162 l0 = split_lo2(bv[i].x, bv[i].y, h0);
            __nv_bfloat162 l1 = split_lo2(bv[i].z, bv[i].w, h1);
            *(__nv_bfloat162*)&Bh[br][bc + i * 4 + 0] = h0;
            *(__nv_bfloat162*)&Bh[br][bc + i * 4 + 2] = h1;
            *(__nv_bfloat162*)&Bl[br][bc + i * 4 + 0] = l0;
            *(__nv_bfloat162*)&Bl[br][bc + i * 4 + 2] = l1;
        }
        __syncthreads();

        // prefetch next tile (overlaps with MMA phase)
        if (k0 + BK < Kd) {
#pragma unroll
            for (int i = 0; i < 4; ++i)
                av[i] = *(const float4*)(Aptr + k0 + BK + ac + i * 4);
#pragma unroll
            for (int i = 0; i < 2; ++i)
                bv[i] = *(const float4*)(Wptr + k0 + BK + bc + i * 4);
        }

        // two k16 steps
#pragma unroll
        for (int ks = 0; ks < 2; ++ks) {
            const unsigned koff = ks * 32;  // 16 elems * 2 bytes
            unsigned ah[2][4], al[2][4], bh[2][4], bl[2][4];
#pragma unroll
            for (int mi = 0; mi < 2; ++mi) {
                ldm_x4(ah[mi], a_addr[mi] + koff);
                ldm_x4(al[mi], a_addr[mi] + koff + lo_off_a);
            }
#pragma unroll
            for (int nj = 0; nj < 2; ++nj) {
                ldm_x4(bh[nj], b_addr[nj] + koff);
                ldm_x4(bl[nj], b_addr[nj] + koff + lo_off_b);
            }
            // sites: nj in {0,1} (16-n groups), s in {0,1} (8-n within)
#pragma unroll
            for (int mi = 0; mi < 2; ++mi) {
#pragma unroll
                for (int nj = 0; nj < 2; ++nj) {
#pragma unroll
                    for (int s = 0; s < 2; ++s) {
                        float* d = acc[mi][nj * 2 + s];
                        unsigned B0h = bh[nj][s], B1h = bh[nj][s + 2];
                        unsigned B0l = bl[nj][s], B1l = bl[nj][s + 2];
                        mma_bf16(d, ah[mi], B0h, B1h);   // hi*hi
                        mma_bf16(d, al[mi], B0h, B1h);   // lo*hi
                        mma_bf16(d, ah[mi], B0l, B1l);   // hi*lo
                    }
                }
            }
        }
    }

    // epilogue
    const int mrow = bm + warp_m * 32 + (lane >> 2);
    const int ncol0 = bn + warp_n * 32 + (lane & 3) * 2;
#pragma unroll
    for (int mi = 0; mi < 2; ++mi) {
#pragma unroll
        for (int site = 0; site < 4; ++site) {
            const int m0 = mrow + mi * 16;
            const int n0 = ncol0 + site * 8;
            float c0 = acc[mi][site][0], c1 = acc[mi][site][1];
            float c2 = acc[mi][site][2], c3 = acc[mi][site][3];
            if (bias) {
                float bb0 = bias[n0], bb1 = bias[n0 + 1];
                c0 += bb0; c1 += bb1; c2 += bb0; c3 += bb1;
            }
            if (res) {
                c0 += res[(long)m0 * N + n0];
                c1 += res[(long)m0 * N + n0 + 1];
                c2 += res[(long)(m0 + 8) * N + n0];
                c3 += res[(long)(m0 + 8) * N + n0 + 1];
            }
            if (relu) {
                c0 = fmaxf(c0, 0.f); c1 = fmaxf(c1, 0.f);
                c2 = fmaxf(c2, 0.f); c3 = fmaxf(c3, 0.f);
            }
            *(float2*)&C[(long)m0 * N + n0]       = make_float2(c0, c1);
            *(float2*)&C[(long)(m0 + 8) * N + n0] = make_float2(c2, c3);
        }
    }
}

// ---------------- flash attention: per (h,b), S-tile=64, L-chunks of 32 ----------------
#define AS 64
#define AL 32

__global__ __launch_bounds__(256) void attn_kernel(
    const float* __restrict__ q, const float* __restrict__ k,
    const float* __restrict__ v, const float* __restrict__ mask,
    float* __restrict__ av)
{
    __shared__ float q_s[AS][65];
    __shared__ float k_s[AL][65];
    __shared__ float v_s[AL][65];
    __shared__ float p_s[AS][AL + 1];
    __shared__ float m_sm[AS], l_sm[AS], c_sm[AS];

    const int hb = blockIdx.y;            // 0..63
    const int h = hb / BATCH, b = hb % BATCH;
    const int s0 = blockIdx.x * AS;
    const int tid = threadIdx.x;
    const int lane = tid & 31, warp = tid >> 5;
    const int tx = tid % 16, ty = tid / 16;

    for (int e = tid; e < AS * 64; e += 256) {
        int r = e >> 6, c = e & 63;
        q_s[r][c] = q[((long)(s0 + r) * BATCH + b) * DMODEL + h * 64 + c];
    }
    if (tid < AS) { m_sm[tid] = -1e30f; l_sm[tid] = 0.0f; }
    float acc[4][4] = {};
    __syncthreads();

    for (int l0 = 0; l0 < LTOT; l0 += AL) {
        for (int e = tid; e < AL * 64; e += 256) {
            int r = e >> 6, c = e & 63;
            long base = ((long)(l0 + r) * BATCH + b) * DMODEL + h * 64 + c;
            k_s[r][c] = k[base];
            v_s[r][c] = v[base];
        }
        __syncthreads();

#pragma unroll
        for (int r0 = 0; r0 < 8; ++r0) {
            int r = warp * 8 + r0;
            float sc = 0.0f;
#pragma unroll
            for (int c = 0; c < 64; ++c) sc += q_s[r][c] * k_s[lane][c];
            sc = sc * 0.125f + mask[(long)(s0 + r) * LTOT + l0 + lane];

            float mx = sc;
#pragma unroll
            for (int o = 16; o > 0; o >>= 1) mx = fmaxf(mx, __shfl_xor_sync(0xffffffffu, mx, o));
            float m_old = m_sm[r];
            float m_new = fmaxf(m_old, mx);
            float p = __expf(sc - m_new);
            float ps = p;
#pragma unroll
            for (int o = 16; o > 0; o >>= 1) ps += __shfl_xor_sync(0xffffffffu, ps, o);
            if (lane == 0) {
                float cf = __expf(m_old - m_new);
                c_sm[r] = cf;
                l_sm[r] = l_sm[r] * cf + ps;
                m_sm[r] = m_new;
            }
            p_s[r][lane] = p;
        }
        __syncthreads();

        float cf0 = c_sm[ty * 4 + 0], cf1 = c_sm[ty * 4 + 1];
        float cf2 = c_sm[ty * 4 + 2], cf3 = c_sm[ty * 4 + 3];
#pragma unroll
        for (int j = 0; j < 4; ++j) {
            acc[0][j] *= cf0; acc[1][j] *= cf1; acc[2][j] *= cf2; acc[3][j] *= cf3;
        }
#pragma unroll
        for (int l = 0; l < AL; ++l) {
            float p0 = p_s[ty * 4 + 0][l], p1 = p_s[ty * 4 + 1][l];
            float p2 = p_s[ty * 4 + 2][l], p3 = p_s[ty * 4 + 3][l];
            float v0 = v_s[l][tx * 4 + 0], v1 = v_s[l][tx * 4 + 1];
            float v2 = v_s[l][tx * 4 + 2], v3 = v_s[l][tx * 4 + 3];
            acc[0][0] += p0 * v0; acc[0][1] += p0 * v1; acc[0][2] += p0 * v2; acc[0][3] += p0 * v3;
            acc[1][0] += p1 * v0; acc[1][1] += p1 * v1; acc[1][2] += p1 * v2; acc[1][3] += p1 * v3;
            acc[2][0] += p2 * v0; acc[2][1] += p2 * v1; acc[2][2] += p2 * v2; acc[2][3] += p2 * v3;
            acc[3][0] += p3 * v0; acc[3][1] += p3 * v1; acc[3][2] += p3 * v2; acc[3][3] += p3 * v3;
        }
        __syncthreads();
    }

#pragma unroll
    for (int i = 0; i < 4; ++i) {
        int r = ty * 4 + i;
        float inv = 1.0f / l_sm[r];
#pragma unroll
        for (int j = 0; j < 4; ++j) {
            av[((long)(s0 + r) * BATCH + b) * DMODEL + h * 64 + tx * 4 + j] = acc[i][j] * inv;
        }
    }
}

// ---------------- LayerNorm over D=1024, one block per row ----------------
__global__ __launch_bounds__(256) void ln_kernel(
    const float* __restrict__ in, float* __restrict__ out,
    const float* __restrict__ g, const float* __restrict__ bta)
{
    const int row = blockIdx.x;
    const float* x = in + (long)row * DMODEL;
    const int tid = threadIdx.x;
    float v[4];
    float s = 0.0f, s2 = 0.0f;
#pragma unroll
    for (int i = 0; i < 4; ++i) {
        v[i] = x[tid + i * 256];
        s += v[i];
        s2 += v[i] * v[i];
    }
    __shared__ float rs[8], rs2[8];
#pragma unroll
    for (int o = 16; o > 0; o >>= 1) {
        s  += __shfl_xor_sync(0xffffffffu, s, o);
        s2 += __shfl_xor_sync(0xffffffffu, s2, o);
    }
    if ((tid & 31) == 0) { rs[tid >> 5] = s; rs2[tid >> 5] = s2; }
    __syncthreads();
    if (tid < 32) {
        s  = (tid < 8) ? rs[tid]  : 0.0f;
        s2 = (tid < 8) ? rs2[tid] : 0.0f;
#pragma unroll
        for (int o = 4; o > 0; o >>= 1) {
            s  += __shfl_xor_sync(0xffffffffu, s, o);
            s2 += __shfl_xor_sync(0xffffffffu, s2, o);
        }
        if (tid == 0) { rs[0] = s; rs2[0] = s2; }
    }
    __syncthreads();
    float mu  = rs[0] * (1.0f / DMODEL);
    float var = rs2[0] * (1.0f / DMODEL) - mu * mu;
    float inv = rsqrtf(var + 1e-5f);
#pragma unroll
    for (int i = 0; i < 4; ++i) {
        int c = tid + i * 256;
        out[(long)row * DMODEL + c] = (v[i] - mu) * inv * g[c] + bta[c];
    }
}

// ---------------- launch ----------------
extern "C" void kernel_launch(void* const* d_in, const int* in_sizes, int n_in,
                              void* d_out, int out_size)
{
    const float* x      = (const float*)d_in[0];
    const float* mask   = (const float*)d_in[1];
    const float* memory = (const float*)d_in[2];

    int o = 3;
    if (n_in >= 16 && in_sizes[3] == 1) o = 4;
    const float* wq   = (const float*)d_in[o + 0];
    const float* wk   = (const float*)d_in[o + 1];
    const float* wv   = (const float*)d_in[o + 2];
    const float* wc   = (const float*)d_in[o + 3];
    const float* w1   = (const float*)d_in[o + 4];
    const float* b1   = (const float*)d_in[o + 5];
    const float* w2   = (const float*)d_in[o + 6];
    const float* b2   = (const float*)d_in[o + 7];
    const float* ln1g = (const float*)d_in[o + 8];
    const float* ln1b = (const float*)d_in[o + 9];
    const float* ln2g = (const float*)d_in[o + 10];
    const float* ln2b = (const float*)d_in[o + 11];
    float* out = (float*)d_out;

    float *q, *k, *v, *av, *upre, *u, *ff;
    cudaGetSymbolAddress((void**)&q,    g_q);
    cudaGetSymbolAddress((void**)&k,    g_k);
    cudaGetSymbolAddress((void**)&v,    g_v);
    cudaGetSymbolAddress((void**)&av,   g_av);
    cudaGetSymbolAddress((void**)&upre, g_upre);
    cudaGetSymbolAddress((void**)&u,    g_u);
    cudaGetSymbolAddress((void**)&ff,   g_ff);

    const int BIG = 1 << 30;
    dim3 thr(256);

    // Q = x @ wq^T
    gemm_tc_kernel<<<dim3(DMODEL / BN, NROWS / BM), thr>>>(
        x, x, BIG, wq, nullptr, nullptr, q, DMODEL, DMODEL, 0);
    // K,V = concat(memory, x) @ w^T
    gemm_tc_kernel<<<dim3(DMODEL / BN, KVROWS / BM), thr>>>(
        memory, x, MEMLEN * NROWS, wk, nullptr, nullptr, k, DMODEL, DMODEL, 0);
    gemm_tc_kernel<<<dim3(DMODEL / BN, KVROWS / BM), thr>>>(
        memory, x, MEMLEN * NROWS, wv, nullptr, nullptr, v, DMODEL, DMODEL, 0);
    // attention
    attn_kernel<<<dim3(SEQ / AS, HEADS * BATCH), thr>>>(q, k, v, mask, av);
    // u_pre = av @ wc^T + x ; u = LN1(u_pre)
    gemm_tc_kernel<<<dim3(DMODEL / BN, NROWS / BM), thr>>>(
        av, av, BIG, wc, nullptr, x, upre, DMODEL, DMODEL, 0);
    ln_kernel<<<NROWS, 256>>>(upre, u, ln1g, ln1b);
    // ff = relu(u @ w1^T + b1)
    gemm_tc_kernel<<<dim3(MFF / BN, NROWS / BM), thr>>>(
        u, u, BIG, w1, b1, nullptr, ff, MFF, DMODEL, 1);
    // z_pre = ff @ w2^T + b2 + u ; out = LN2(z_pre)
    gemm_tc_kernel<<<dim3(DMODEL / BN, NROWS / BM), thr>>>(
        ff, ff, BIG, w2, b2, u, out, DMODEL, MFF, 0);
    ln_kernel<<<NROWS, 256>>>(out, out, ln2g, ln2b);
}

// round 7
// speedup vs baseline: 2.3868x; 1.5151x over previous
#include <cuda_runtime.h>
#include <cuda_bf16.h>
#include <math.h>

// Problem constants
#define HEADS 16
#define DMODEL 1024
#define KDIM 64
#define MFF 4096
#define MEMLEN 3
#define SEQ 512
#define BATCH 4
#define NROWS (SEQ * BATCH)            // 2048
#define LTOT ((MEMLEN + 1) * SEQ)      // 2048
#define KVROWS (LTOT * BATCH)          // 8192

// ---------------- scratch (no allocation allowed) ----------------
__device__ float g_q[NROWS * DMODEL];
__device__ float g_k[KVROWS * DMODEL];
__device__ float g_v[KVROWS * DMODEL];
__device__ float g_av[NROWS * DMODEL];
__device__ float g_upre[NROWS * DMODEL];
__device__ float g_u[NROWS * DMODEL];
__device__ float g_ff[NROWS * MFF];

// ---------------- shared helpers ----------------
__device__ __forceinline__ unsigned smem_u32(const void* p) {
    return (unsigned)__cvta_generic_to_shared(p);
}

__device__ __forceinline__ void ldm_x4(unsigned* r, unsigned addr) {
    asm volatile("ldmatrix.sync.aligned.m8n8.x4.shared.b16 {%0,%1,%2,%3}, [%4];"
                 : "=r"(r[0]), "=r"(r[1]), "=r"(r[2]), "=r"(r[3]) : "r"(addr));
}

__device__ __forceinline__ void ldm_x4_t(unsigned* r, unsigned addr) {
    asm volatile("ldmatrix.sync.aligned.m8n8.x4.trans.shared.b16 {%0,%1,%2,%3}, [%4];"
                 : "=r"(r[0]), "=r"(r[1]), "=r"(r[2]), "=r"(r[3]) : "r"(addr));
}

__device__ __forceinline__ void mma_bf16(float* d, const unsigned* a,
                                         unsigned b0, unsigned b1) {
    asm volatile("mma.sync.aligned.m16n8k16.row.col.f32.bf16.bf16.f32 "
                 "{%0,%1,%2,%3}, {%4,%5,%6,%7}, {%8,%9}, {%0,%1,%2,%3};"
                 : "+f"(d[0]), "+f"(d[1]), "+f"(d[2]), "+f"(d[3])
                 : "r"(a[0]), "r"(a[1]), "r"(a[2]), "r"(a[3]), "r"(b0), "r"(b1));
}

__device__ __forceinline__ __nv_bfloat162 split_hi2(float x, float y) {
    return __nv_bfloat162(__float2bfloat16_rn(x), __float2bfloat16_rn(y));
}
__device__ __forceinline__ __nv_bfloat162 split_lo2(float x, float y,
                                                    __nv_bfloat162 h) {
    return __nv_bfloat162(
        __float2bfloat16_rn(x - __bfloat162float(h.x)),
        __float2bfloat16_rn(y - __bfloat162float(h.y)));
}
__device__ __forceinline__ unsigned pack_hi2(float a, float b) {
    __nv_bfloat162 t = split_hi2(a, b);
    return reinterpret_cast<unsigned&>(t);
}
__device__ __forceinline__ unsigned pack_lo2(float a, float b, unsigned hibits) {
    __nv_bfloat162 h = reinterpret_cast<__nv_bfloat162&>(hibits);
    __nv_bfloat162 t = split_lo2(a, b, h);
    return reinterpret_cast<unsigned&>(t);
}

// =======================================================================
// Tensor-core GEMM with split-bf16 (hi+lo) for fp32-class accuracy.
// =======================================================================
#define BM 128
#define BN 64
#define BK 32
#define BKP 40   // padded k-stride (80 bytes) -> conflict-free ldmatrix

__global__ __launch_bounds__(256) void gemm_tc_kernel(
    const float* __restrict__ A, const float* __restrict__ A2, int split,
    const float* __restrict__ W, const float* __restrict__ bias,
    const float* __restrict__ res, float* __restrict__ C,
    int N, int Kd, int relu)
{
    __shared__ __align__(16) __nv_bfloat16 Ah[BM][BKP];
    __shared__ __align__(16) __nv_bfloat16 Al[BM][BKP];
    __shared__ __align__(16) __nv_bfloat16 Bh[BN][BKP];
    __shared__ __align__(16) __nv_bfloat16 Bl[BN][BKP];

    const int tid  = threadIdx.x;
    const int lane = tid & 31;
    const int warp = tid >> 5;
    const int warp_m = warp >> 1;
    const int warp_n = warp & 1;
    const int bm = blockIdx.y * BM;
    const int bn = blockIdx.x * BN;

    const int ar = tid >> 1;
    const int ac = (tid & 1) * 16;
    const int br = tid >> 2;
    const int bc = (tid & 3) * 8;

    const int garow = bm + ar;
    const float* Aptr = (garow < split) ? (A + (long)garow * Kd)
                                        : (A2 + (long)(garow - split) * Kd);
    const float* Wptr = W + (long)(bn + br) * Kd;

    float acc[2][4][4];
#pragma unroll
    for (int i = 0; i < 2; ++i)
#pragma unroll
        for (int j = 0; j < 4; ++j)
#pragma unroll
            for (int l = 0; l < 4; ++l) acc[i][j][l] = 0.0f;

    const int lr16 = lane & 15;
    const int lkh  = (lane >> 4) * 8;
    unsigned a_addr[2], b_addr[2];
#pragma unroll
    for (int mi = 0; mi < 2; ++mi)
        a_addr[mi] = smem_u32(&Ah[warp_m * 32 + mi * 16 + lr16][lkh]);
#pragma unroll
    for (int nj = 0; nj < 2; ++nj)
        b_addr[nj] = smem_u32(&Bh[warp_n * 32 + nj * 16 + lr16][lkh]);
    const unsigned lo_off_a = (unsigned)((char*)&Al[0][0] - (char*)&Ah[0][0]);
    const unsigned lo_off_b = (unsigned)((char*)&Bl[0][0] - (char*)&Bh[0][0]);

    float4 av[4], bv[2];
#pragma unroll
    for (int i = 0; i < 4; ++i) av[i] = *(const float4*)(Aptr + ac + i * 4);
#pragma unroll
    for (int i = 0; i < 2; ++i) bv[i] = *(const float4*)(Wptr + bc + i * 4);

    for (int k0 = 0; k0 < Kd; k0 += BK) {
        __syncthreads();
#pragma unroll
        for (int i = 0; i < 4; ++i) {
            __nv_bfloat162 h0 = split_hi2(av[i].x, av[i].y);
            __nv_bfloat162 h1 = split_hi2(av[i].z, av[i].w);
            __nv_bfloat162 l0 = split_lo2(av[i].x, av[i].y, h0);
            __nv_bfloat162 l1 = split_lo2(av[i].z, av[i].w, h1);
            *(__nv_bfloat162*)&Ah[ar][ac + i * 4 + 0] = h0;
            *(__nv_bfloat162*)&Ah[ar][ac + i * 4 + 2] = h1;
            *(__nv_bfloat162*)&Al[ar][ac + i * 4 + 0] = l0;
            *(__nv_bfloat162*)&Al[ar][ac + i * 4 + 2] = l1;
        }
#pragma unroll
        for (int i = 0; i < 2; ++i) {
            __nv_bfloat162 h0 = split_hi2(bv[i].x, bv[i].y);
            __nv_bfloat162 h1 = split_hi2(bv[i].z, bv[i].w);
            __nv_bfloat162 l0 = split_lo2(bv[i].x, bv[i].y, h0);
            __nv_bfloat162 l1 = split_lo2(bv[i].z, bv[i].w, h1);
            *(__nv_bfloat162*)&Bh[br][bc + i * 4 + 0] = h0;
            *(__nv_bfloat162*)&Bh[br][bc + i * 4 + 2] = h1;
            *(__nv_bfloat162*)&Bl[br][bc + i * 4 + 0] = l0;
            *(__nv_bfloat162*)&Bl[br][bc + i * 4 + 2] = l1;
        }
        __syncthreads();

        if (k0 + BK < Kd) {
#pragma unroll
            for (int i = 0; i < 4; ++i)
                av[i] = *(const float4*)(Aptr + k0 + BK + ac + i * 4);
#pragma unroll
            for (int i = 0; i < 2; ++i)
                bv[i] = *(const float4*)(Wptr + k0 + BK + bc + i * 4);
        }

#pragma unroll
        for (int ks = 0; ks < 2; ++ks) {
            const unsigned koff = ks * 32;
            unsigned ah[2][4], al[2][4], bh[2][4], bl[2][4];
#pragma unroll
            for (int mi = 0; mi < 2; ++mi) {
                ldm_x4(ah[mi], a_addr[mi] + koff);
                ldm_x4(al[mi], a_addr[mi] + koff + lo_off_a);
            }
#pragma unroll
            for (int nj = 0; nj < 2; ++nj) {
                ldm_x4(bh[nj], b_addr[nj] + koff);
                ldm_x4(bl[nj], b_addr[nj] + koff + lo_off_b);
            }
#pragma unroll
            for (int mi = 0; mi < 2; ++mi) {
#pragma unroll
                for (int nj = 0; nj < 2; ++nj) {
#pragma unroll
                    for (int s = 0; s < 2; ++s) {
                        float* d = acc[mi][nj * 2 + s];
                        unsigned B0h = bh[nj][s], B1h = bh[nj][s + 2];
                        unsigned B0l = bl[nj][s], B1l = bl[nj][s + 2];
                        mma_bf16(d, ah[mi], B0h, B1h);
                        mma_bf16(d, al[mi], B0h, B1h);
                        mma_bf16(d, ah[mi], B0l, B1l);
                    }
                }
            }
        }
    }

    const int mrow = bm + warp_m * 32 + (lane >> 2);
    const int ncol0 = bn + warp_n * 32 + (lane & 3) * 2;
#pragma unroll
    for (int mi = 0; mi < 2; ++mi) {
#pragma unroll
        for (int site = 0; site < 4; ++site) {
            const int m0 = mrow + mi * 16;
            const int n0 = ncol0 + site * 8;
            float c0 = acc[mi][site][0], c1 = acc[mi][site][1];
            float c2 = acc[mi][site][2], c3 = acc[mi][site][3];
            if (bias) {
                float bb0 = bias[n0], bb1 = bias[n0 + 1];
                c0 += bb0; c1 += bb1; c2 += bb0; c3 += bb1;
            }
            if (res) {
                c0 += res[(long)m0 * N + n0];
                c1 += res[(long)m0 * N + n0 + 1];
                c2 += res[(long)(m0 + 8) * N + n0];
                c3 += res[(long)(m0 + 8) * N + n0 + 1];
            }
            if (relu) {
                c0 = fmaxf(c0, 0.f); c1 = fmaxf(c1, 0.f);
                c2 = fmaxf(c2, 0.f); c3 = fmaxf(c3, 0.f);
            }
            *(float2*)&C[(long)m0 * N + n0]       = make_float2(c0, c1);
            *(float2*)&C[(long)(m0 + 8) * N + n0] = make_float2(c2, c3);
        }
    }
}

// =======================================================================
// Tensor-core flash attention, split-bf16 (hi+lo) for QK and PV.
// Block: 64 S-rows x one (h,b). 4 warps x 16 rows. L-chunks of 64.
// =======================================================================
#define ATP 72   // padded row stride (144B) -> conflict-free ldmatrix

__global__ __launch_bounds__(128) void attn_tc_kernel(
    const float* __restrict__ q, const float* __restrict__ k,
    const float* __restrict__ v, const float* __restrict__ mask,
    float* __restrict__ av)
{
    extern __shared__ __align__(16) __nv_bfloat16 sm[];
    __nv_bfloat16* Qh = sm;
    __nv_bfloat16* Ql = sm + 1 * 64 * ATP;
    __nv_bfloat16* Kh = sm + 2 * 64 * ATP;
    __nv_bfloat16* Kl = sm + 3 * 64 * ATP;
    __nv_bfloat16* Vh = sm + 4 * 64 * ATP;
    __nv_bfloat16* Vl = sm + 5 * 64 * ATP;

    const int hb = blockIdx.y;
    const int h = hb / BATCH, b = hb % BATCH;
    const int s0 = blockIdx.x * 64;
    const int tid = threadIdx.x;
    const int lane = tid & 31, warp = tid >> 5;

    // ---- load Q tile (64x64), split hi/lo ----
    for (int e = tid; e < 1024; e += 128) {
        int row = e >> 4, col = (e & 15) << 2;
        float4 qv = *(const float4*)&q[((long)(s0 + row) * BATCH + b) * DMODEL + h * 64 + col];
        __nv_bfloat162 h0 = split_hi2(qv.x, qv.y), h1 = split_hi2(qv.z, qv.w);
        __nv_bfloat162 l0 = split_lo2(qv.x, qv.y, h0), l1 = split_lo2(qv.z, qv.w, h1);
        *(__nv_bfloat162*)&Qh[row * ATP + col + 0] = h0;
        *(__nv_bfloat162*)&Qh[row * ATP + col + 2] = h1;
        *(__nv_bfloat162*)&Ql[row * ATP + col + 0] = l0;
        *(__nv_bfloat162*)&Ql[row * ATP + col + 2] = l1;
    }
    __syncthreads();

    // ---- hoist Q A-fragments (loop-invariant) ----
    unsigned qfh[4][4], qfl[4][4];
    {
        unsigned qb = smem_u32(&Qh[(warp * 16 + (lane & 15)) * ATP + (lane >> 4) * 8]);
        const unsigned qlo = (unsigned)((char*)Ql - (char*)Qh);
#pragma unroll
        for (int ks = 0; ks < 4; ++ks) {
            ldm_x4(qfh[ks], qb + ks * 32);
            ldm_x4(qfl[ks], qb + ks * 32 + qlo);
        }
    }

    float oacc[8][4];
#pragma unroll
    for (int n = 0; n < 8; ++n)
#pragma unroll
        for (int j = 0; j < 4; ++j) oacc[n][j] = 0.0f;
    float m0 = -1e30f, m1 = -1e30f, ls0 = 0.0f, ls1 = 0.0f;

    const unsigned krow = smem_u32(&Kh[(lane & 15) * ATP + (lane >> 4) * 8]);
    const unsigned vrow = smem_u32(&Vh[(lane & 15) * ATP + (lane >> 4) * 8]);
    const unsigned kloff = (unsigned)((char*)Kl - (char*)Kh);
    const unsigned vloff = (unsigned)((char*)Vl - (char*)Vh);

    const int r0g = s0 + warp * 16 + (lane >> 2);
    const float* mrow0 = mask + (long)r0g * LTOT + (lane & 3) * 2;
    const float* mrow1 = mrow0 + 8L * LTOT;

    for (int l0 = 0; l0 < LTOT; l0 += 64) {
        __syncthreads();
        // load K,V chunk (64x64 each), split hi/lo
        for (int e = tid; e < 1024; e += 128) {
            int row = e >> 4, col = (e & 15) << 2;
            long base = ((long)(l0 + row) * BATCH + b) * DMODEL + h * 64 + col;
            float4 kv = *(const float4*)&k[base];
            float4 vv = *(const float4*)&v[base];
            __nv_bfloat162 kh0 = split_hi2(kv.x, kv.y), kh1 = split_hi2(kv.z, kv.w);
            __nv_bfloat162 kl0 = split_lo2(kv.x, kv.y, kh0), kl1 = split_lo2(kv.z, kv.w, kh1);
            __nv_bfloat162 vh0 = split_hi2(vv.x, vv.y), vh1 = split_hi2(vv.z, vv.w);
            __nv_bfloat162 vl0 = split_lo2(vv.x, vv.y, vh0), vl1 = split_lo2(vv.z, vv.w, vh1);
            *(__nv_bfloat162*)&Kh[row * ATP + col + 0] = kh0;
            *(__nv_bfloat162*)&Kh[row * ATP + col + 2] = kh1;
            *(__nv_bfloat162*)&Kl[row * ATP + col + 0] = kl0;
            *(__nv_bfloat162*)&Kl[row * ATP + col + 2] = kl1;
            *(__nv_bfloat162*)&Vh[row * ATP + col + 0] = vh0;
            *(__nv_bfloat162*)&Vh[row * ATP + col + 2] = vh1;
            *(__nv_bfloat162*)&Vl[row * ATP + col + 0] = vl0;
            *(__nv_bfloat162*)&Vl[row * ATP + col + 2] = vl1;
        }
        __syncthreads();

        // ---- S = Q K^T (split 3-pass) ----
        float sacc[8][4];
#pragma unroll
        for (int n = 0; n < 8; ++n)
#pragma unroll
            for (int j = 0; j < 4; ++j) sacc[n][j] = 0.0f;

#pragma unroll
        for (int ks = 0; ks < 4; ++ks) {
#pragma unroll
            for (int ng = 0; ng < 4; ++ng) {
                unsigned kbh[4], kbl[4];
                unsigned addr = krow + (unsigned)((ng * 16 * ATP + ks * 16) * 2);
                ldm_x4(kbh, addr);
                ldm_x4(kbl, addr + kloff);
#pragma unroll
                for (int s = 0; s < 2; ++s) {
                    float* d = sacc[ng * 2 + s];
                    mma_bf16(d, qfh[ks], kbh[s], kbh[s + 2]);
                    mma_bf16(d, qfl[ks], kbh[s], kbh[s + 2]);
                    mma_bf16(d, qfh[ks], kbl[s], kbl[s + 2]);
                }
            }
        }

        // ---- scale + mask + online softmax ----
        float mx0 = -1e30f, mx1 = -1e30f;
#pragma unroll
        for (int n = 0; n < 8; ++n) {
            float2 mk0 = *(const float2*)&mrow0[l0 + n * 8];
            float2 mk1 = *(const float2*)&mrow1[l0 + n * 8];
            sacc[n][0] = sacc[n][0] * 0.125f + mk0.x;
            sacc[n][1] = sacc[n][1] * 0.125f + mk0.y;
            sacc[n][2] = sacc[n][2] * 0.125f + mk1.x;
            sacc[n][3] = sacc[n][3] * 0.125f + mk1.y;
            mx0 = fmaxf(mx0, fmaxf(sacc[n][0], sacc[n][1]));
            mx1 = fmaxf(mx1, fmaxf(sacc[n][2], sacc[n][3]));
        }
        mx0 = fmaxf(mx0, __shfl_xor_sync(0xffffffffu, mx0, 1));
        mx0 = fmaxf(mx0, __shfl_xor_sync(0xffffffffu, mx0, 2));
        mx1 = fmaxf(mx1, __shfl_xor_sync(0xffffffffu, mx1, 1));
        mx1 = fmaxf(mx1, __shfl_xor_sync(0xffffffffu, mx1, 2));
        float m0n = fmaxf(m0, mx0), m1n = fmaxf(m1, mx1);
        float c0 = __expf(m0 - m0n), c1 = __expf(m1 - m1n);
        m0 = m0n; m1 = m1n;

        float ps0 = 0.0f, ps1 = 0.0f;
#pragma unroll
        for (int n = 0; n < 8; ++n) {
            sacc[n][0] = __expf(sacc[n][0] - m0n);
            sacc[n][1] = __expf(sacc[n][1] - m0n);
            sacc[n][2] = __expf(sacc[n][2] - m1n);
            sacc[n][3] = __expf(sacc[n][3] - m1n);
            ps0 += sacc[n][0] + sacc[n][1];
            ps1 += sacc[n][2] + sacc[n][3];
        }
        ps0 += __shfl_xor_sync(0xffffffffu, ps0, 1);
        ps0 += __shfl_xor_sync(0xffffffffu, ps0, 2);
        ps1 += __shfl_xor_sync(0xffffffffu, ps1, 1);
        ps1 += __shfl_xor_sync(0xffffffffu, ps1, 2);
        ls0 = ls0 * c0 + ps0;
        ls1 = ls1 * c1 + ps1;

#pragma unroll
        for (int n = 0; n < 8; ++n) {
            oacc[n][0] *= c0; oacc[n][1] *= c0;
            oacc[n][2] *= c1; oacc[n][3] *= c1;
        }

        // ---- P -> hi/lo A-fragments (accumulator layout == A layout) ----
        unsigned pah[4][4], pal[4][4];
#pragma unroll
        for (int kp = 0; kp < 4; ++kp) {
            const float* t0 = sacc[2 * kp];
            const float* t1 = sacc[2 * kp + 1];
            pah[kp][0] = pack_hi2(t0[0], t0[1]);
            pah[kp][1] = pack_hi2(t0[2], t0[3]);
            pah[kp][2] = pack_hi2(t1[0], t1[1]);
            pah[kp][3] = pack_hi2(t1[2], t1[3]);
            pal[kp][0] = pack_lo2(t0[0], t0[1], pah[kp][0]);
            pal[kp][1] = pack_lo2(t0[2], t0[3], pah[kp][1]);
            pal[kp][2] = pack_lo2(t1[0], t1[1], pah[kp][2]);
            pal[kp][3] = pack_lo2(t1[2], t1[3], pah[kp][3]);
        }

        // ---- O += P V (split 3-pass), V via ldmatrix.trans ----
#pragma unroll
        for (int kp = 0; kp < 4; ++kp) {
#pragma unroll
            for (int ng = 0; ng < 4; ++ng) {
                unsigned vbh[4], vbl[4];
                unsigned addr = vrow + (unsigned)((kp * 16 * ATP + ng * 16) * 2);
                ldm_x4_t(vbh, addr);
                ldm_x4_t(vbl, addr + vloff);
#pragma unroll
                for (int s = 0; s < 2; ++s) {
                    float* d = oacc[ng * 2 + s];
                    mma_bf16(d, pah[kp], vbh[s * 2], vbh[s * 2 + 1]);
                    mma_bf16(d, pal[kp], vbh[s * 2], vbh[s * 2 + 1]);
                    mma_bf16(d, pah[kp], vbl[s * 2], vbl[s * 2 + 1]);
                }
            }
        }
    }

    // ---- write O ----
    float inv0 = 1.0f / ls0, inv1 = 1.0f / ls1;
#pragma unroll
    for (int n = 0; n < 8; ++n) {
        int col = h * 64 + n * 8 + (lane & 3) * 2;
        *(float2*)&av[((long)r0g * BATCH + b) * DMODEL + col] =
            make_float2(oacc[n][0] * inv0, oacc[n][1] * inv0);
        *(float2*)&av[((long)(r0g + 8) * BATCH + b) * DMODEL + col] =
            make_float2(oacc[n][2] * inv1, oacc[n][3] * inv1);
    }
}

#define ATTN_SMEM (6 * 64 * ATP * 2)

// ---------------- LayerNorm over D=1024, one block per row ----------------
__global__ __launch_bounds__(256) void ln_kernel(
    const float* __restrict__ in, float* __restrict__ out,
    const float* __restrict__ g, const float* __restrict__ bta)
{
    const int row = blockIdx.x;
    const float* x = in + (long)row * DMODEL;
    const int tid = threadIdx.x;
    float v[4];
    float s = 0.0f, s2 = 0.0f;
#pragma unroll
    for (int i = 0; i < 4; ++i) {
        v[i] = x[tid + i * 256];
        s += v[i];
        s2 += v[i] * v[i];
    }
    __shared__ float rs[8], rs2[8];
#pragma unroll
    for (int o = 16; o > 0; o >>= 1) {
        s  += __shfl_xor_sync(0xffffffffu, s, o);
        s2 += __shfl_xor_sync(0xffffffffu, s2, o);
    }
    if ((tid & 31) == 0) { rs[tid >> 5] = s; rs2[tid >> 5] = s2; }
    __syncthreads();
    if (tid < 32) {
        s  = (tid < 8) ? rs[tid]  : 0.0f;
        s2 = (tid < 8) ? rs2[tid] : 0.0f;
#pragma unroll
        for (int o = 4; o > 0; o >>= 1) {
            s  += __shfl_xor_sync(0xffffffffu, s, o);
            s2 += __shfl_xor_sync(0xffffffffu, s2, o);
        }
        if (tid == 0) { rs[0] = s; rs2[0] = s2; }
    }
    __syncthreads();
    float mu  = rs[0] * (1.0f / DMODEL);
    float var = rs2[0] * (1.0f / DMODEL) - mu * mu;
    float inv = rsqrtf(var + 1e-5f);
#pragma unroll
    for (int i = 0; i < 4; ++i) {
        int c = tid + i * 256;
        out[(long)row * DMODEL + c] = (v[i] - mu) * inv * g[c] + bta[c];
    }
}

// ---------------- launch ----------------
extern "C" void kernel_launch(void* const* d_in, const int* in_sizes, int n_in,
                              void* d_out, int out_size)
{
    const float* x      = (const float*)d_in[0];
    const float* mask   = (const float*)d_in[1];
    const float* memory = (const float*)d_in[2];

    int o = 3;
    if (n_in >= 16 && in_sizes[3] == 1) o = 4;
    const float* wq   = (const float*)d_in[o + 0];
    const float* wk   = (const float*)d_in[o + 1];
    const float* wv   = (const float*)d_in[o + 2];
    const float* wc   = (const float*)d_in[o + 3];
    const float* w1   = (const float*)d_in[o + 4];
    const float* b1   = (const float*)d_in[o + 5];
    const float* w2   = (const float*)d_in[o + 6];
    const float* b2   = (const float*)d_in[o + 7];
    const float* ln1g = (const float*)d_in[o + 8];
    const float* ln1b = (const float*)d_in[o + 9];
    const float* ln2g = (const float*)d_in[o + 10];
    const float* ln2b = (const float*)d_in[o + 11];
    float* out = (float*)d_out;

    float *q, *k, *v, *av, *upre, *u, *ff;
    cudaGetSymbolAddress((void**)&q,    g_q);
    cudaGetSymbolAddress((void**)&k,    g_k);
    cudaGetSymbolAddress((void**)&v,    g_v);
    cudaGetSymbolAddress((void**)&av,   g_av);
    cudaGetSymbolAddress((void**)&upre, g_upre);
    cudaGetSymbolAddress((void**)&u,    g_u);
    cudaGetSymbolAddress((void**)&ff,   g_ff);

    // Unconditional (no static guard): enqueues no work, capture-safe,
    // identical on every call.
    cudaFuncSetAttribute(attn_tc_kernel,
                         cudaFuncAttributeMaxDynamicSharedMemorySize, ATTN_SMEM);

    const int BIG = 1 << 30;
    dim3 thr(256);

    // Q = x @ wq^T
    gemm_tc_kernel<<<dim3(DMODEL / BN, NROWS / BM), thr>>>(
        x, x, BIG, wq, nullptr, nullptr, q, DMODEL, DMODEL, 0);
    // K,V = concat(memory, x) @ w^T
    gemm_tc_kernel<<<dim3(DMODEL / BN, KVROWS / BM), thr>>>(
        memory, x, MEMLEN * NROWS, wk, nullptr, nullptr, k, DMODEL, DMODEL, 0);
    gemm_tc_kernel<<<dim3(DMODEL / BN, KVROWS / BM), thr>>>(
        memory, x, MEMLEN * NROWS, wv, nullptr, nullptr, v, DMODEL, DMODEL, 0);
    // attention (tensor-core flash)
    attn_tc_kernel<<<dim3(SEQ / 64, HEADS * BATCH), 128, ATTN_SMEM>>>(
        q, k, v, mask, av);
    // u_pre = av @ wc^T + x ; u = LN1(u_pre)
    gemm_tc_kernel<<<dim3(DMODEL / BN, NROWS / BM), thr>>>(
        av, av, BIG, wc, nullptr, x, upre, DMODEL, DMODEL, 0);
    ln_kernel<<<NROWS, 256>>>(upre, u, ln1g, ln1b);
    // ff = relu(u @ w1^T + b1)
    gemm_tc_kernel<<<dim3(MFF / BN, NROWS / BM), thr>>>(
        u, u, BIG, w1, b1, nullptr, ff, MFF, DMODEL, 1);
    // z_pre = ff @ w2^T + b2 + u ; out = LN2(z_pre)
    gemm_tc_kernel<<<dim3(DMODEL / BN, NROWS / BM), thr>>>(
        ff, ff, BIG, w2, b2, u, out, DMODEL, MFF, 0);
    ln_kernel<<<NROWS, 256>>>(out, out, ln2g, ln2b);
}

// round 9
// speedup vs baseline: 3.0122x; 1.2621x over previous
#include <cuda_runtime.h>
#include <cuda_bf16.h>
#include <math.h>

// Problem constants
#define HEADS 16
#define DMODEL 1024
#define KDIM 64
#define MFF 4096
#define MEMLEN 3
#define SEQ 512
#define BATCH 4
#define NROWS (SEQ * BATCH)            // 2048
#define LTOT ((MEMLEN + 1) * SEQ)      // 2048
#define KVROWS (LTOT * BATCH)          // 8192
#define HKD (HEADS * KDIM * DMODEL)    // 1048576 (1M) elems per qkv/c weight

// ---------------- scratch (no allocation allowed) ----------------
// fp32
__device__ float g_upre[NROWS * DMODEL];
__device__ float g_u[NROWS * DMODEL];
// bf16 hi/lo pairs
__device__ __nv_bfloat16 g_wh[12 * 1024 * 1024];
__device__ __nv_bfloat16 g_wl[12 * 1024 * 1024];
__device__ __nv_bfloat16 g_xmh[KVROWS * DMODEL];
__device__ __nv_bfloat16 g_xml[KVROWS * DMODEL];
__device__ __nv_bfloat16 g_qh[NROWS * DMODEL];
__device__ __nv_bfloat16 g_ql[NROWS * DMODEL];
__device__ __nv_bfloat16 g_kh[KVROWS * DMODEL];
__device__ __nv_bfloat16 g_kl[KVROWS * DMODEL];
__device__ __nv_bfloat16 g_vh[KVROWS * DMODEL];
__device__ __nv_bfloat16 g_vl[KVROWS * DMODEL];
__device__ __nv_bfloat16 g_avh[NROWS * DMODEL];
__device__ __nv_bfloat16 g_avl[NROWS * DMODEL];
__device__ __nv_bfloat16 g_uh[NROWS * DMODEL];
__device__ __nv_bfloat16 g_ul[NROWS * DMODEL];
__device__ __nv_bfloat16 g_ffh[NROWS * MFF];
__device__ __nv_bfloat16 g_ffl[NROWS * MFF];

// weight offsets (elems) inside g_wh/g_wl
#define WQ_OFF 0
#define WK_OFF (1 * HKD)
#define WV_OFF (2 * HKD)
#define WC_OFF (3 * HKD)
#define W1_OFF (4 * HKD)
#define W2_OFF (8 * HKD)

// ---------------- helpers ----------------
__device__ __forceinline__ unsigned smem_u32(const void* p) {
    return (unsigned)__cvta_generic_to_shared(p);
}
__device__ __forceinline__ void cp_async16(unsigned dst, const void* src) {
    asm volatile("cp.async.cg.shared.global [%0], [%1], 16;" :: "r"(dst), "l"(src));
}
__device__ __forceinline__ void cp_commit() {
    asm volatile("cp.async.commit_group;");
}
__device__ __forceinline__ void cp_wait0() {
    asm volatile("cp.async.wait_group 0;");
}
__device__ __forceinline__ void ldm_x4(unsigned* r, unsigned addr) {
    asm volatile("ldmatrix.sync.aligned.m8n8.x4.shared.b16 {%0,%1,%2,%3}, [%4];"
                 : "=r"(r[0]), "=r"(r[1]), "=r"(r[2]), "=r"(r[3]) : "r"(addr));
}
__device__ __forceinline__ void ldm_x4_t(unsigned* r, unsigned addr) {
    asm volatile("ldmatrix.sync.aligned.m8n8.x4.trans.shared.b16 {%0,%1,%2,%3}, [%4];"
                 : "=r"(r[0]), "=r"(r[1]), "=r"(r[2]), "=r"(r[3]) : "r"(addr));
}
__device__ __forceinline__ void mma_bf16(float* d, const unsigned* a,
                                         unsigned b0, unsigned b1) {
    asm volatile("mma.sync.aligned.m16n8k16.row.col.f32.bf16.bf16.f32 "
                 "{%0,%1,%2,%3}, {%4,%5,%6,%7}, {%8,%9}, {%0,%1,%2,%3};"
                 : "+f"(d[0]), "+f"(d[1]), "+f"(d[2]), "+f"(d[3])
                 : "r"(a[0]), "r"(a[1]), "r"(a[2]), "r"(a[3]), "r"(b0), "r"(b1));
}
__device__ __forceinline__ __nv_bfloat162 split_hi2(float x, float y) {
    return __nv_bfloat162(__float2bfloat16_rn(x), __float2bfloat16_rn(y));
}
__device__ __forceinline__ __nv_bfloat162 split_lo2(float x, float y,
                                                    __nv_bfloat162 h) {
    return __nv_bfloat162(
        __float2bfloat16_rn(x - __bfloat162float(h.x)),
        __float2bfloat16_rn(y - __bfloat162float(h.y)));
}
__device__ __forceinline__ unsigned pack_hi2(float a, float b) {
    __nv_bfloat162 t = split_hi2(a, b);
    return reinterpret_cast<unsigned&>(t);
}
__device__ __forceinline__ unsigned pack_lo2(float a, float b, unsigned hibits) {
    __nv_bfloat162 h = reinterpret_cast<__nv_bfloat162&>(hibits);
    __nv_bfloat162 t = split_lo2(a, b, h);
    return reinterpret_cast<unsigned&>(t);
}

// ---------------- fp32 -> (hi,lo) bf16 split ----------------
__global__ __launch_bounds__(256) void split_kernel(
    const float* __restrict__ in, __nv_bfloat16* __restrict__ hi,
    __nv_bfloat16* __restrict__ lo, int n4)
{
    int i = blockIdx.x * blockDim.x + threadIdx.x;
    if (i >= n4) return;
    float4 v = ((const float4*)in)[i];
    __nv_bfloat162 h0 = split_hi2(v.x, v.y), h1 = split_hi2(v.z, v.w);
    __nv_bfloat162 l0 = split_lo2(v.x, v.y, h0), l1 = split_lo2(v.z, v.w, h1);
    ((__nv_bfloat162*)hi)[i * 2 + 0] = h0;
    ((__nv_bfloat162*)hi)[i * 2 + 1] = h1;
    ((__nv_bfloat162*)lo)[i * 2 + 0] = l0;
    ((__nv_bfloat162*)lo)[i * 2 + 1] = l1;
}

// =======================================================================
// bf16 hi/lo GEMM, cp.async double-buffered.
// C[M,N] = (Ah+Al)[M,Kd] @ (Wh+Wl)[N,Kd]^T (+bias)(+res)(relu)
// Output: fp32 (Cf) or hi/lo bf16 (Ch,Cl).
// BM=128, BN=64, BK=32, 256 threads (8 warps = 4m x 2n).
// =======================================================================
#define BM 128
#define BN 64
#define BK 32
#define BKP 40        // padded k-stride in elems (80B)
// stage layout (elems): Ah[128*40] Al[128*40] Bh[64*40] Bl[64*40]
#define G_AHO 0
#define G_ALO (128 * BKP)
#define G_BHO (256 * BKP)
#define G_BLO (320 * BKP)
#define G_STAGE (384 * BKP)                 // 15360 elems
#define G_SMEM (2 * G_STAGE * 2)            // 61440 bytes

__global__ __launch_bounds__(256) void gemm_bf_kernel(
    const __nv_bfloat16* __restrict__ Ah_g, const __nv_bfloat16* __restrict__ Al_g,
    const __nv_bfloat16* __restrict__ Wh_g, const __nv_bfloat16* __restrict__ Wl_g,
    const float* __restrict__ bias, const float* __restrict__ res,
    float* __restrict__ Cf, __nv_bfloat16* __restrict__ Ch,
    __nv_bfloat16* __restrict__ Cl, int N, int Kd, int relu)
{
    extern __shared__ __align__(16) __nv_bfloat16 gsm[];
    const unsigned sbase = smem_u32(gsm);

    const int tid  = threadIdx.x;
    const int lane = tid & 31;
    const int warp = tid >> 5;
    const int warp_m = warp >> 1;
    const int warp_n = warp & 1;
    const int bm = blockIdx.y * BM;
    const int bn = blockIdx.x * BN;

    // load mapping: 16B chunk = 8 bf16
    const int a_row0 = tid >> 2;
    const int a_kc0  = tid & 3;

    float acc[2][4][4];
#pragma unroll
    for (int i = 0; i < 2; ++i)
#pragma unroll
        for (int j = 0; j < 4; ++j)
#pragma unroll
            for (int l = 0; l < 4; ++l) acc[i][j][l] = 0.0f;

    const int lr16 = lane & 15;
    const int lkh  = (lane >> 4) * 8;
    unsigned aoff[2], boff[2];
#pragma unroll
    for (int mi = 0; mi < 2; ++mi)
        aoff[mi] = (unsigned)((G_AHO + (warp_m * 32 + mi * 16 + lr16) * BKP + lkh) * 2);
#pragma unroll
    for (int nj = 0; nj < 2; ++nj)
        boff[nj] = (unsigned)((G_BHO + (warp_n * 32 + nj * 16 + lr16) * BKP + lkh) * 2);
    const unsigned ALD = (G_ALO - G_AHO) * 2;   // bytes
    const unsigned BLD = (G_BLO - G_BHO) * 2;

    const int T = Kd / BK;

    // stage load: 6 cp.async per thread
    auto issue_tile = [&](int k0, int s) {
        unsigned st = sbase + (unsigned)(s * G_STAGE * 2);
#pragma unroll
        for (int i = 0; i < 2; ++i) {
            int c = tid + i * 256;           // 0..511
            int row = c >> 2, kc = c & 3;
            long gsrc = (long)(bm + row) * Kd + k0 + kc * 8;
            unsigned d = st + (unsigned)((row * BKP + kc * 8) * 2);
            cp_async16(d + G_AHO * 2, Ah_g + gsrc);
            cp_async16(d + G_ALO * 2, Al_g + gsrc);
        }
        {
            int row = a_row0, kc = a_kc0;    // 256 chunks: rows 0..63
            long gsrc = (long)(bn + row) * Kd + k0 + kc * 8;
            unsigned d = st + (unsigned)((row * BKP + kc * 8) * 2);
            cp_async16(d + G_BHO * 2, Wh_g + gsrc);
            cp_async16(d + G_BLO * 2, Wl_g + gsrc);
        }
        cp_commit();
    };

    issue_tile(0, 0);

    for (int t = 0; t < T; ++t) {
        cp_wait0();
        __syncthreads();
        if (t + 1 < T) issue_tile((t + 1) * BK, (t + 1) & 1);

        const unsigned stB = sbase + (unsigned)((t & 1) * G_STAGE * 2);
#pragma unroll
        for (int ks = 0; ks < 2; ++ks) {
            const unsigned koff = ks * 32;   // 16 elems * 2B
            unsigned ah[2][4], al[2][4], bh[2][4], bl[2][4];
#pragma unroll
            for (int mi = 0; mi < 2; ++mi) {
                unsigned a = stB + aoff[mi] + koff;
                ldm_x4(ah[mi], a);
                ldm_x4(al[mi], a + ALD);
            }
#pragma unroll
            for (int nj = 0; nj < 2; ++nj) {
                unsigned bA = stB + boff[nj] + koff;
                ldm_x4(bh[nj], bA);
                ldm_x4(bl[nj], bA + BLD);
            }
#pragma unroll
            for (int mi = 0; mi < 2; ++mi) {
#pragma unroll
                for (int nj = 0; nj < 2; ++nj) {
#pragma unroll
                    for (int s = 0; s < 2; ++s) {
                        float* d = acc[mi][nj * 2 + s];
                        unsigned B0h = bh[nj][s], B1h = bh[nj][s + 2];
                        unsigned B0l = bl[nj][s], B1l = bl[nj][s + 2];
                        mma_bf16(d, ah[mi], B0h, B1h);
                        mma_bf16(d, al[mi], B0h, B1h);
                        mma_bf16(d, ah[mi], B0l, B1l);
                    }
                }
            }
        }
    }

    // epilogue
    const int mrow = bm + warp_m * 32 + (lane >> 2);
    const int ncol0 = bn + warp_n * 32 + (lane & 3) * 2;
#pragma unroll
    for (int mi = 0; mi < 2; ++mi) {
#pragma unroll
        for (int site = 0; site < 4; ++site) {
            const int m0 = mrow + mi * 16;
            const int n0 = ncol0 + site * 8;
            float c0 = acc[mi][site][0], c1 = acc[mi][site][1];
            float c2 = acc[mi][site][2], c3 = acc[mi][site][3];
            if (bias) {
                float bb0 = bias[n0], bb1 = bias[n0 + 1];
                c0 += bb0; c1 += bb1; c2 += bb0; c3 += bb1;
            }
            if (res) {
                c0 += res[(long)m0 * N + n0];
                c1 += res[(long)m0 * N + n0 + 1];
                c2 += res[(long)(m0 + 8) * N + n0];
                c3 += res[(long)(m0 + 8) * N + n0 + 1];
            }
            if (relu) {
                c0 = fmaxf(c0, 0.f); c1 = fmaxf(c1, 0.f);
                c2 = fmaxf(c2, 0.f); c3 = fmaxf(c3, 0.f);
            }
            if (Cf) {
                *(float2*)&Cf[(long)m0 * N + n0]       = make_float2(c0, c1);
                *(float2*)&Cf[(long)(m0 + 8) * N + n0] = make_float2(c2, c3);
            } else {
                __nv_bfloat162 h0 = split_hi2(c0, c1), h1 = split_hi2(c2, c3);
                __nv_bfloat162 l0 = split_lo2(c0, c1, h0), l1 = split_lo2(c2, c3, h1);
                *(__nv_bfloat162*)&Ch[(long)m0 * N + n0]       = h0;
                *(__nv_bfloat162*)&Ch[(long)(m0 + 8) * N + n0] = h1;
                *(__nv_bfloat162*)&Cl[(long)m0 * N + n0]       = l0;
                *(__nv_bfloat162*)&Cl[(long)(m0 + 8) * N + n0] = l1;
            }
        }
    }
}

// =======================================================================
// Tensor-core flash attention, bf16 hi/lo inputs, cp.async 2-stage K/V.
// Block: 64 S-rows x one (h,b). 4 warps x 16 rows. L-chunks of 64.
// smem (elems): Qh[64*72] Ql[64*72] | stage{0,1}: Kh Kl Vh Vl (64*72 each)
// =======================================================================
#define ATP 72
#define A_QELEMS (64 * ATP)                 // 4608
#define A_STAGE0 (2 * A_QELEMS)             // 9216
#define A_STAGEE (4 * A_QELEMS)             // 18432 elems per stage
#define ATTN_SMEM ((A_STAGE0 + 2 * A_STAGEE) * 2)   // 92160 bytes

__global__ __launch_bounds__(128) void attn_tc_kernel(
    const __nv_bfloat16* __restrict__ qh, const __nv_bfloat16* __restrict__ ql,
    const __nv_bfloat16* __restrict__ kh, const __nv_bfloat16* __restrict__ kl,
    const __nv_bfloat16* __restrict__ vh, const __nv_bfloat16* __restrict__ vl,
    const float* __restrict__ mask,
    __nv_bfloat16* __restrict__ avh, __nv_bfloat16* __restrict__ avl)
{
    extern __shared__ __align__(16) __nv_bfloat16 asm_[];
    const unsigned sbase = smem_u32(asm_);

    const int hb = blockIdx.y;
    const int h = hb / BATCH, b = hb % BATCH;
    const int s0 = blockIdx.x * 64;
    const int tid = threadIdx.x;
    const int lane = tid & 31, warp = tid >> 5;

    // ---- Q load (1024 chunks of 16B over 2 halves) ----
#pragma unroll
    for (int i = 0; i < 8; ++i) {
        int c = tid + i * 128;
        int half = c >> 9, cc = c & 511;
        int row = cc >> 3, kc = cc & 7;
        const __nv_bfloat16* src = (half ? ql : qh) +
            ((long)(s0 + row) * BATCH + b) * DMODEL + h * 64 + kc * 8;
        unsigned d = sbase + (unsigned)((half * A_QELEMS + row * ATP + kc * 8) * 2);
        cp_async16(d, src);
    }
    cp_commit();

    // ---- KV stage loads: 2048 chunks of 16B (arrays Kh,Kl,Vh,Vl) ----
    auto issue_kv = [&](int l0, int s) {
        unsigned st = sbase + (unsigned)((A_STAGE0 + s * A_STAGEE) * 2);
#pragma unroll
        for (int i = 0; i < 16; ++i) {
            int c = tid + i * 128;
            int arr = c >> 9, cc = c & 511;
            int row = cc >> 3, kc = cc & 7;
            const __nv_bfloat16* base =
                (arr == 0) ? kh : (arr == 1) ? kl : (arr == 2) ? vh : vl;
            const __nv_bfloat16* src = base +
                ((long)(l0 + row) * BATCH + b) * DMODEL + h * 64 + kc * 8;
            unsigned d = st + (unsigned)((arr * A_QELEMS + row * ATP + kc * 8) * 2);
            cp_async16(d, src);
        }
        cp_commit();
    };

    issue_kv(0, 0);
    cp_wait0();
    __syncthreads();

    // ---- hoist Q fragments ----
    unsigned qfh[4][4], qfl[4][4];
    {
        unsigned qb = sbase + (unsigned)(((warp * 16 + (lane & 15)) * ATP + (lane >> 4) * 8) * 2);
        const unsigned qlo = A_QELEMS * 2;
#pragma unroll
        for (int ks = 0; ks < 4; ++ks) {
            ldm_x4(qfh[ks], qb + ks * 32);
            ldm_x4(qfl[ks], qb + ks * 32 + qlo);
        }
    }

    float oacc[8][4];
#pragma unroll
    for (int n = 0; n < 8; ++n)
#pragma unroll
        for (int j = 0; j < 4; ++j) oacc[n][j] = 0.0f;
    float m0 = -1e30f, m1 = -1e30f, ls0 = 0.0f, ls1 = 0.0f;

    const unsigned fragoff = (unsigned)(((lane & 15) * ATP + (lane >> 4) * 8) * 2);
    const unsigned KLD = A_QELEMS * 2;       // Kl - Kh bytes
    const unsigned VOFF = 2 * A_QELEMS * 2;  // Vh - Kh bytes

    const int r0g = s0 + warp * 16 + (lane >> 2);
    const float* mrow0 = mask + (long)r0g * LTOT + (lane & 3) * 2;
    const float* mrow1 = mrow0 + 8L * LTOT;

    const int NIT = LTOT / 64;
    for (int it = 0; it < NIT; ++it) {
        if (it + 1 < NIT) issue_kv((it + 1) * 64, (it + 1) & 1);

        const unsigned stB = sbase + (unsigned)((A_STAGE0 + (it & 1) * A_STAGEE) * 2);
        const unsigned krow = stB + fragoff;
        const unsigned vrow = stB + VOFF + fragoff;
        const int l0 = it * 64;

        // ---- S = Q K^T ----
        float sacc[8][4];
#pragma unroll
        for (int n = 0; n < 8; ++n)
#pragma unroll
            for (int j = 0; j < 4; ++j) sacc[n][j] = 0.0f;

#pragma unroll
        for (int ks = 0; ks < 4; ++ks) {
#pragma unroll
            for (int ng = 0; ng < 4; ++ng) {
                unsigned kbh[4], kbl[4];
                unsigned addr = krow + (unsigned)((ng * 16 * ATP + ks * 16) * 2);
                ldm_x4(kbh, addr);
                ldm_x4(kbl, addr + KLD);
#pragma unroll
                for (int s = 0; s < 2; ++s) {
                    float* d = sacc[ng * 2 + s];
                    mma_bf16(d, qfh[ks], kbh[s], kbh[s + 2]);
                    mma_bf16(d, qfl[ks], kbh[s], kbh[s + 2]);
                    mma_bf16(d, qfh[ks], kbl[s], kbl[s + 2]);
                }
            }
        }

        // ---- scale + mask + online softmax ----
        float mx0 = -1e30f, mx1 = -1e30f;
#pragma unroll
        for (int n = 0; n < 8; ++n) {
            float2 mk0 = *(const float2*)&mrow0[l0 + n * 8];
            float2 mk1 = *(const float2*)&mrow1[l0 + n * 8];
            sacc[n][0] = sacc[n][0] * 0.125f + mk0.x;
            sacc[n][1] = sacc[n][1] * 0.125f + mk0.y;
            sacc[n][2] = sacc[n][2] * 0.125f + mk1.x;
            sacc[n][3] = sacc[n][3] * 0.125f + mk1.y;
            mx0 = fmaxf(mx0, fmaxf(sacc[n][0], sacc[n][1]));
            mx1 = fmaxf(mx1, fmaxf(sacc[n][2], sacc[n][3]));
        }
        mx0 = fmaxf(mx0, __shfl_xor_sync(0xffffffffu, mx0, 1));
        mx0 = fmaxf(mx0, __shfl_xor_sync(0xffffffffu, mx0, 2));
        mx1 = fmaxf(mx1, __shfl_xor_sync(0xffffffffu, mx1, 1));
        mx1 = fmaxf(mx1, __shfl_xor_sync(0xffffffffu, mx1, 2));
        float m0n = fmaxf(m0, mx0), m1n = fmaxf(m1, mx1);
        float c0 = __expf(m0 - m0n), c1 = __expf(m1 - m1n);
        m0 = m0n; m1 = m1n;

        float ps0 = 0.0f, ps1 = 0.0f;
#pragma unroll
        for (int n = 0; n < 8; ++n) {
            sacc[n][0] = __expf(sacc[n][0] - m0n);
            sacc[n][1] = __expf(sacc[n][1] - m0n);
            sacc[n][2] = __expf(sacc[n][2] - m1n);
            sacc[n][3] = __expf(sacc[n][3] - m1n);
            ps0 += sacc[n][0] + sacc[n][1];
            ps1 += sacc[n][2] + sacc[n][3];
        }
        ps0 += __shfl_xor_sync(0xffffffffu, ps0, 1);
        ps0 += __shfl_xor_sync(0xffffffffu, ps0, 2);
        ps1 += __shfl_xor_sync(0xffffffffu, ps1, 1);
        ps1 += __shfl_xor_sync(0xffffffffu, ps1, 2);
        ls0 = ls0 * c0 + ps0;
        ls1 = ls1 * c1 + ps1;

#pragma unroll
        for (int n = 0; n < 8; ++n) {
            oacc[n][0] *= c0; oacc[n][1] *= c0;
            oacc[n][2] *= c1; oacc[n][3] *= c1;
        }

        // ---- P -> hi/lo A-fragments ----
        unsigned pah[4][4], pal[4][4];
#pragma unroll
        for (int kp = 0; kp < 4; ++kp) {
            const float* t0 = sacc[2 * kp];
            const float* t1 = sacc[2 * kp + 1];
            pah[kp][0] = pack_hi2(t0[0], t0[1]);
            pah[kp][1] = pack_hi2(t0[2], t0[3]);
            pah[kp][2] = pack_hi2(t1[0], t1[1]);
            pah[kp][3] = pack_hi2(t1[2], t1[3]);
            pal[kp][0] = pack_lo2(t0[0], t0[1], pah[kp][0]);
            pal[kp][1] = pack_lo2(t0[2], t0[3], pah[kp][1]);
            pal[kp][2] = pack_lo2(t1[0], t1[1], pah[kp][2]);
            pal[kp][3] = pack_lo2(t1[2], t1[3], pah[kp][3]);
        }

        // ---- O += P V ----
#pragma unroll
        for (int kp = 0; kp < 4; ++kp) {
#pragma unroll
            for (int ng = 0; ng < 4; ++ng) {
                unsigned vbh[4], vbl[4];
                unsigned addr = vrow + (unsigned)((kp * 16 * ATP + ng * 16) * 2);
                ldm_x4_t(vbh, addr);
                ldm_x4_t(vbl, addr + KLD);
#pragma unroll
                for (int s = 0; s < 2; ++s) {
                    float* d = oacc[ng * 2 + s];
                    mma_bf16(d, pah[kp], vbh[s * 2], vbh[s * 2 + 1]);
                    mma_bf16(d, pal[kp], vbh[s * 2], vbh[s * 2 + 1]);
                    mma_bf16(d, pah[kp], vbl[s * 2], vbl[s * 2 + 1]);
                }
            }
        }

        if (it + 1 < NIT) {
            cp_wait0();
            __syncthreads();
        }
    }

    // ---- write O as hi/lo bf16 ----
    float inv0 = 1.0f / ls0, inv1 = 1.0f / ls1;
#pragma unroll
    for (int n = 0; n < 8; ++n) {
        int col = h * 64 + n * 8 + (lane & 3) * 2;
        long i0 = ((long)r0g * BATCH + b) * DMODEL + col;
        long i1 = ((long)(r0g + 8) * BATCH + b) * DMODEL + col;
        float a0 = oacc[n][0] * inv0, a1 = oacc[n][1] * inv0;
        float a2 = oacc[n][2] * inv1, a3 = oacc[n][3] * inv1;
        __nv_bfloat162 h0 = split_hi2(a0, a1), h1 = split_hi2(a2, a3);
        __nv_bfloat162 l0 = split_lo2(a0, a1, h0), l1 = split_lo2(a2, a3, h1);
        *(__nv_bfloat162*)&avh[i0] = h0;
        *(__nv_bfloat162*)&avh[i1] = h1;
        *(__nv_bfloat162*)&avl[i0] = l0;
        *(__nv_bfloat162*)&avl[i1] = l1;
    }
}

// ---------------- LayerNorm over D=1024 (+ optional hi/lo bf16 out) ----
__global__ __launch_bounds__(256) void ln_kernel(
    const float* __restrict__ in, float* __restrict__ out,
    const float* __restrict__ g, const float* __restrict__ bta,
    __nv_bfloat16* __restrict__ oh, __nv_bfloat16* __restrict__ ol)
{
    const int row = blockIdx.x;
    const float* x = in + (long)row * DMODEL;
    const int tid = threadIdx.x;
    float v[4];
    float s = 0.0f, s2 = 0.0f;
#pragma unroll
    for (int i = 0; i < 4; ++i) {
        v[i] = x[tid + i * 256];
        s += v[i];
        s2 += v[i] * v[i];
    }
    __shared__ float rs[8], rs2[8];
#pragma unroll
    for (int o = 16; o > 0; o >>= 1) {
        s  += __shfl_xor_sync(0xffffffffu, s, o);
        s2 += __shfl_xor_sync(0xffffffffu, s2, o);
    }
    if ((tid & 31) == 0) { rs[tid >> 5] = s; rs2[tid >> 5] = s2; }
    __syncthreads();
    if (tid < 32) {
        s  = (tid < 8) ? rs[tid]  : 0.0f;
        s2 = (tid < 8) ? rs2[tid] : 0.0f;
#pragma unroll
        for (int o = 4; o > 0; o >>= 1) {
            s  += __shfl_xor_sync(0xffffffffu, s, o);
            s2 += __shfl_xor_sync(0xffffffffu, s2, o);
        }
        if (tid == 0) { rs[0] = s; rs2[0] = s2; }
    }
    __syncthreads();
    float mu  = rs[0] * (1.0f / DMODEL);
    float var = rs2[0] * (1.0f / DMODEL) - mu * mu;
    float inv = rsqrtf(var + 1e-5f);
#pragma unroll
    for (int i = 0; i < 4; ++i) {
        int c = tid + i * 256;
        float y = (v[i] - mu) * inv * g[c] + bta[c];
        out[(long)row * DMODEL + c] = y;
        if (oh) {
            __nv_bfloat16 hb = __float2bfloat16_rn(y);
            oh[(long)row * DMODEL + c] = hb;
            ol[(long)row * DMODEL + c] =
                __float2bfloat16_rn(y - __bfloat162float(hb));
        }
    }
}

// ---------------- launch ----------------
extern "C" void kernel_launch(void* const* d_in, const int* in_sizes, int n_in,
                              void* d_out, int out_size)
{
    const float* x      = (const float*)d_in[0];
    const float* mask   = (const float*)d_in[1];
    const float* memory = (const float*)d_in[2];

    int o = 3;
    if (n_in >= 16 && in_sizes[3] == 1) o = 4;
    const float* wq   = (const float*)d_in[o + 0];
    const float* wk   = (const float*)d_in[o + 1];
    const float* wv   = (const float*)d_in[o + 2];
    const float* wc   = (const float*)d_in[o + 3];
    const float* w1   = (const float*)d_in[o + 4];
    const float* b1   = (const float*)d_in[o + 5];
    const float* w2   = (const float*)d_in[o + 6];
    const float* b2   = (const float*)d_in[o + 7];
    const float* ln1g = (const float*)d_in[o + 8];
    const float* ln1b = (const float*)d_in[o + 9];
    const float* ln2g = (const float*)d_in[o + 10];
    const float* ln2b = (const float*)d_in[o + 11];
    float* out = (float*)d_out;

    float *upre, *u;
    __nv_bfloat16 *wh, *wl, *xmh, *xml, *qh, *ql, *kh, *kl, *vh, *vl;
    __nv_bfloat16 *avh, *avl, *uh, *ul, *ffh, *ffl;
    cudaGetSymbolAddress((void**)&upre, g_upre);
    cudaGetSymbolAddress((void**)&u,    g_u);
    cudaGetSymbolAddress((void**)&wh,   g_wh);
    cudaGetSymbolAddress((void**)&wl,   g_wl);
    cudaGetSymbolAddress((void**)&xmh,  g_xmh);
    cudaGetSymbolAddress((void**)&xml,  g_xml);
    cudaGetSymbolAddress((void**)&qh,   g_qh);
    cudaGetSymbolAddress((void**)&ql,   g_ql);
    cudaGetSymbolAddress((void**)&kh,   g_kh);
    cudaGetSymbolAddress((void**)&kl,   g_kl);
    cudaGetSymbolAddress((void**)&vh,   g_vh);
    cudaGetSymbolAddress((void**)&vl,   g_vl);
    cudaGetSymbolAddress((void**)&avh,  g_avh);
    cudaGetSymbolAddress((void**)&avl,  g_avl);
    cudaGetSymbolAddress((void**)&uh,   g_uh);
    cudaGetSymbolAddress((void**)&ul,   g_ul);
    cudaGetSymbolAddress((void**)&ffh,  g_ffh);
    cudaGetSymbolAddress((void**)&ffl,  g_ffl);

    cudaFuncSetAttribute(gemm_bf_kernel,
                         cudaFuncAttributeMaxDynamicSharedMemorySize, G_SMEM);
    cudaFuncSetAttribute(attn_tc_kernel,
                         cudaFuncAttributeMaxDynamicSharedMemorySize, ATTN_SMEM);

    dim3 thr(256);
    const long XOFF = (long)MEMLEN * NROWS * DMODEL;   // x rows start in xm

    // ---- converts ----
    split_kernel<<<1024, 256>>>(wq, wh + WQ_OFF, wl + WQ_OFF, HKD / 4);
    split_kernel<<<1024, 256>>>(wk, wh + WK_OFF, wl + WK_OFF, HKD / 4);
    split_kernel<<<1024, 256>>>(wv, wh + WV_OFF, wl + WV_OFF, HKD / 4);
    split_kernel<<<1024, 256>>>(wc, wh + WC_OFF, wl + WC_OFF, HKD / 4);
    split_kernel<<<4096, 256>>>(w1, wh + W1_OFF, wl + W1_OFF, (MFF * DMODEL) / 4);
    split_kernel<<<4096, 256>>>(w2, wh + W2_OFF, wl + W2_OFF, (MFF * DMODEL) / 4);
    split_kernel<<<6144, 256>>>(memory, xmh, xml, (int)(XOFF / 4));
    split_kernel<<<2048, 256>>>(x, xmh + XOFF, xml + XOFF, (NROWS * DMODEL) / 4);

    // ---- QKV GEMMs (bf16 out) ----
    gemm_bf_kernel<<<dim3(DMODEL / BN, NROWS / BM), thr, G_SMEM>>>(
        xmh + XOFF, xml + XOFF, wh + WQ_OFF, wl + WQ_OFF,
        nullptr, nullptr, nullptr, qh, ql, DMODEL, DMODEL, 0);
    gemm_bf_kernel<<<dim3(DMODEL / BN, KVROWS / BM), thr, G_SMEM>>>(
        xmh, xml, wh + WK_OFF, wl + WK_OFF,
        nullptr, nullptr, nullptr, kh, kl, DMODEL, DMODEL, 0);
    gemm_bf_kernel<<<dim3(DMODEL / BN, KVROWS / BM), thr, G_SMEM>>>(
        xmh, xml, wh + WV_OFF, wl + WV_OFF,
        nullptr, nullptr, nullptr, vh, vl, DMODEL, DMODEL, 0);

    // ---- attention ----
    attn_tc_kernel<<<dim3(SEQ / 64, HEADS * BATCH), 128, ATTN_SMEM>>>(
        qh, ql, kh, kl, vh, vl, mask, avh, avl);

    // ---- u_pre = av @ wc^T + x (fp32), LN1 -> u (fp32 + bf16) ----
    gemm_bf_kernel<<<dim3(DMODEL / BN, NROWS / BM), thr, G_SMEM>>>(
        avh, avl, wh + WC_OFF, wl + WC_OFF,
        nullptr, x, upre, nullptr, nullptr, DMODEL, DMODEL, 0);
    ln_kernel<<<NROWS, 256>>>(upre, u, ln1g, ln1b, uh, ul);

    // ---- ff = relu(u @ w1^T + b1) (bf16 out) ----
    gemm_bf_kernel<<<dim3(MFF / BN, NROWS / BM), thr, G_SMEM>>>(
        uh, ul, wh + W1_OFF, wl + W1_OFF,
        b1, nullptr, nullptr, ffh, ffl, MFF, DMODEL, 1);

    // ---- z_pre = ff @ w2^T + b2 + u (fp32), LN2 in-place ----
    gemm_bf_kernel<<<dim3(DMODEL / BN, NROWS / BM), thr, G_SMEM>>>(
        ffh, ffl, wh + W2_OFF, wl + W2_OFF,
        b2, u, out, nullptr, nullptr, DMODEL, MFF, 0);
    ln_kernel<<<NROWS, 256>>>(out, out, ln2g, ln2b, nullptr, nullptr);
}